// round 13
// baseline (speedup 1.0000x reference)
#include <cuda_runtime.h>
#include <cuda_fp16.h>
#include <cstdint>

// ============================================================
// Attention1D fully fused: LN -> QKV GEMM -> 8-head window attention
//   -> output GEMM. One kernel, persistent register accumulators.
// fp16 mma.sync m16n8k16 everywhere (incl. attention: c->a/b frag repack,
// movmatrix V-transpose, block-diagonal PV MMA).
// R11: K=128 chunks (16 barriers), uint4-paired B fragments (LDS.128),
// cp.async.cg staging. tcgen05 unavailable (harness PTX = compute_103).
// ============================================================

#define FULLM 0xffffffffu

// B1 frags: [cid(16)=h*2+qq][ks(8)][ntp(6)][lane(32)][q4(4)] uint32  (384KB)
//   q4: {nt=2ntp:b0,b1, nt=2ntp+1:b0,b1}
__device__ __align__(16) uint32_t g_w1t[196608];
// B2 frags: [h(8)][ks2(2)][ntp(16)][lane(32)][q4(4)] uint32          (128KB)
__device__ __align__(16) uint32_t g_w2t[65536];

static __device__ __forceinline__ void mma16(float* c, uint32_t a0, uint32_t a1,
                                             uint32_t a2, uint32_t a3,
                                             uint32_t b0, uint32_t b1) {
    asm volatile(
        "mma.sync.aligned.m16n8k16.row.col.f32.f16.f16.f32 "
        "{%0,%1,%2,%3}, {%4,%5,%6,%7}, {%8,%9}, {%0,%1,%2,%3};"
        : "+f"(c[0]), "+f"(c[1]), "+f"(c[2]), "+f"(c[3])
        : "r"(a0), "r"(a1), "r"(a2), "r"(a3), "r"(b0), "r"(b1));
}
static __device__ __forceinline__ uint32_t h2u(float a, float b) {
    __half2 h = __floats2half2_rn(a, b);
    return *(uint32_t*)&h;
}
static __device__ __forceinline__ uint32_t movm(uint32_t s) {
    uint32_t d;
    asm("movmatrix.sync.aligned.m8n8.trans.b16 %0, %1;" : "=r"(d) : "r"(s));
    return d;
}
static __device__ __forceinline__ uint32_t smem_u32(const void* p) {
    uint32_t a;
    asm("{ .reg .u64 t; cvta.to.shared.u64 t, %1; cvt.u32.u64 %0, t; }" : "=r"(a) : "l"(p));
    return a;
}
#define CP16(dst, src) \
    asm volatile("cp.async.cg.shared.global [%0], [%1], 16;" :: "r"(dst), "l"(src))
#define CP_COMMIT() asm volatile("cp.async.commit_group;" ::: "memory")
#define CP_WAIT(n)  asm volatile("cp.async.wait_group %0;" :: "n"(n) : "memory")

// ---------------- weight prep (fp16 round + fragment-order transpose) ----------------
// Attention scale (32^-0.5) folded into the q-columns of w1.
__global__ void prep_w1(const float* __restrict__ wqkv) {
    int p = blockIdx.x * 256 + threadIdx.x;          // < 196608
    int q4   = p & 3;
    int lane = (p >> 2) & 31;
    int rest = p >> 7;                               // 0..1535
    int ntp = rest % 6;
    int r2  = rest / 6;                              // 0..255
    int ks  = r2 & 7;
    int cid = r2 >> 3;                               // 0..15
    int h = cid >> 1, qq = cid & 1;
    int t = lane & 3, g = lane >> 2;
    int nt  = 2 * ntp + (q4 >> 1);
    int b01 = q4 & 1;
    int k0 = qq * 128 + ks * 16 + b01 * 8 + 2 * t;   // K index
    int s = nt >> 2;                                 // 0=q,1=k,2=v
    int col = s * 256 + h * 32 + (nt & 3) * 8 + g;   // qkv column
    float sc = (s == 0) ? 0.17677669529663689f : 1.0f;
    g_w1t[p] = h2u(wqkv[k0 * 768 + col] * sc, wqkv[(k0 + 1) * 768 + col] * sc);
}
__global__ void prep_w2(const float* __restrict__ wout) {
    int p = blockIdx.x * 256 + threadIdx.x;          // < 65536
    int q4   = p & 3;
    int lane = (p >> 2) & 31;
    int ntp  = (p >> 7) & 15;
    int ks2  = (p >> 11) & 1;
    int h    = p >> 12;
    int t = lane & 3, g = lane >> 2;
    int nt  = 2 * ntp + (q4 >> 1);
    int b01 = q4 & 1;
    int k0 = h * 32 + ks2 * 16 + b01 * 8 + 2 * t;
    int n  = nt * 8 + g;
    g_w2t[p] = h2u(wout[k0 * 256 + n], wout[(k0 + 1) * 256 + n]);
}

// ============================================================
// Fused kernel. 256 threads (8 warps), warp = m16 rows.
// smem: xn 64KB | B1 ring 3x24KB | B2 ring 2x16KB  = 172032 B
// ============================================================
#define B1_SLOT 24576
#define B2_SLOT 16384
#define SM_B1   65536
#define SM_B2   (65536 + 3 * B1_SLOT)
#define K1_SMEM (65536 + 3 * B1_SLOT + 2 * B2_SLOT)

__global__ void __launch_bounds__(256, 1) attn_fused(
    const float* __restrict__ x, const float* __restrict__ lnw,
    const float* __restrict__ lnb, const float* __restrict__ relt,
    float* __restrict__ out)
{
    extern __shared__ __align__(16) char smem[];
    __half* const sxn = (__half*)smem;                // 32768 halves
    const int tid  = threadIdx.x;
    const int wid  = tid >> 5;
    const int lane = tid & 31;
    const int g = lane >> 2, t = lane & 3;
    const int cta = blockIdx.x;
    const uint32_t smem_b1 = smem_u32(smem) + SM_B1;
    const uint32_t smem_b2 = smem_u32(smem) + SM_B2;

    // stage B1 chunk cid (24KB linear) into ring slot cid%3;
    // withB2: bundle B2 for head h2 (16KB) into the same commit group.
    auto stage = [&](int cid2, bool withB2, int h2) {
        uint32_t dst = smem_b1 + (uint32_t)(cid2 % 3) * (uint32_t)B1_SLOT + (uint32_t)tid * 16u;
        const char* src = (const char*)g_w1t + cid2 * B1_SLOT + tid * 16;
        #pragma unroll
        for (int i = 0; i < 6; ++i) CP16(dst + i * 4096u, src + i * 4096);
        if (withB2) {
            uint32_t d2 = smem_b2 + (uint32_t)(h2 & 1) * (uint32_t)B2_SLOT + (uint32_t)tid * 16u;
            const char* s2 = (const char*)g_w2t + h2 * B2_SLOT + tid * 16;
            #pragma unroll
            for (int i = 0; i < 4; ++i) CP16(d2 + i * 4096u, s2 + i * 4096);
        }
        CP_COMMIT();
    };
    stage(0, true, 0);                                // chunk 0 + B2_0
    stage(1, false, 0);

    // ---- LayerNorm -> xor-swizzled row-major fp16 xn (overlaps cp.async) ----
    {
        const float* xr = x + (size_t)cta * 128 * 256;
        const float4 w0 = *(const float4*)(lnw + lane * 4);
        const float4 w1 = *(const float4*)(lnw + 128 + lane * 4);
        const float4 b0 = *(const float4*)(lnb + lane * 4);
        const float4 b1 = *(const float4*)(lnb + 128 + lane * 4);
        #pragma unroll 2
        for (int rr = 0; rr < 16; ++rr) {
            const int r = wid * 16 + rr;
            const float4 xa = *(const float4*)(xr + r * 256 + lane * 4);
            const float4 xb = *(const float4*)(xr + r * 256 + 128 + lane * 4);
            float s  = xa.x + xa.y + xa.z + xa.w + xb.x + xb.y + xb.z + xb.w;
            float ss = xa.x*xa.x + xa.y*xa.y + xa.z*xa.z + xa.w*xa.w
                     + xb.x*xb.x + xb.y*xb.y + xb.z*xb.z + xb.w*xb.w;
            #pragma unroll
            for (int o2 = 16; o2; o2 >>= 1) {
                s  += __shfl_xor_sync(FULLM, s,  o2);
                ss += __shfl_xor_sync(FULLM, ss, o2);
            }
            const float mu   = s * (1.0f / 256.0f);
            const float rstd = rsqrtf(ss * (1.0f / 256.0f) - mu * mu + 1e-5f);
            const int srw = (r & 7) << 3;             // half-index XOR swizzle
            uint2 pa, pb;
            pa.x = h2u((xa.x - mu) * rstd * w0.x + b0.x, (xa.y - mu) * rstd * w0.y + b0.y);
            pa.y = h2u((xa.z - mu) * rstd * w0.z + b0.z, (xa.w - mu) * rstd * w0.w + b0.w);
            pb.x = h2u((xb.x - mu) * rstd * w1.x + b1.x, (xb.y - mu) * rstd * w1.y + b1.y);
            pb.y = h2u((xb.z - mu) * rstd * w1.z + b1.z, (xb.w - mu) * rstd * w1.w + b1.w);
            *(uint2*)(sxn + r * 256 + ((lane * 4) ^ srw))         = pa;
            *(uint2*)(sxn + r * 256 + ((128 + lane * 4) ^ srw))   = pb;
        }
    }

    float acc[12][4];                 // GEMM1 accum (q|k|v of current head)
    #pragma unroll
    for (int n = 0; n < 12; ++n)
        #pragma unroll
        for (int e = 0; e < 4; ++e) acc[n][e] = 0.0f;

    float acc2[32][4];                // GEMM2 accum (m16 x n256, all heads)
    #pragma unroll
    for (int n = 0; n < 32; ++n)
        #pragma unroll
        for (int e = 0; e < 4; ++e) acc2[n][e] = 0.0f;

    const int w16 = wid * 16;
    const __half* const xrow0 = sxn + (w16 + g) * 256;      // row g
    const __half* const xrow1 = xrow0 + 8 * 256;            // row g+8
    const int sx = g << 3;
    float bj0 = 0.0f, bj1 = 0.0f;     // rel-pos bias (slot g vs slots 2t / 2t+1)

    #pragma unroll 1
    for (int cid = 0; cid < 16; ++cid) {
        const int h = cid >> 1, qq = cid & 1;
        if (cid == 15) { CP_WAIT(0); } else { CP_WAIT(1); }
        __syncthreads();                              // chunk cid (and its B2) ready
        if (cid + 2 < 16) stage(cid + 2, ((cid + 2) & 1) == 0, (cid + 2) >> 1);

        if (qq == 0) {
            const int j0 = 2 * t, j1 = 2 * t + 1;
            const int r0 = (g >= 1 && j0 >= 1) ? (g - j0 + 6) : 13;
            const int r1 = (g >= 1) ? (g - j1 + 6) : 13;
            bj0 = __ldg(relt + r0 * 8 + h);
            bj1 = __ldg(relt + r1 * 8 + h);
        }

        // ---- GEMM1 on chunk: K=128 (8 k16-steps), warp tile m16 x n96 ----
        const uint4* const bw4 = (const uint4*)(smem + SM_B1 + (cid % 3) * B1_SLOT);
        #pragma unroll
        for (int ks = 0; ks < 8; ++ks) {
            const int c0 = qq * 128 + ks * 16 + 2 * t;
            const uint32_t a0 = *(const uint32_t*)(xrow0 + (c0 ^ sx));
            const uint32_t a1 = *(const uint32_t*)(xrow1 + (c0 ^ sx));
            const uint32_t a2 = *(const uint32_t*)(xrow0 + ((c0 + 8) ^ sx));
            const uint32_t a3 = *(const uint32_t*)(xrow1 + ((c0 + 8) ^ sx));
            #pragma unroll
            for (int ntp = 0; ntp < 6; ++ntp) {
                const uint4 fb = bw4[(ks * 6 + ntp) * 32 + lane];
                mma16(acc[2*ntp],     a0, a1, a2, a3, fb.x, fb.y);
                mma16(acc[2*ntp + 1], a0, a1, a2, a3, fb.z, fb.w);
            }
        }

        if (qq == 1) {
            // ================== attention for head h (MMA-based) ==================
            uint32_t aq[2][4];
            #pragma unroll
            for (int ks = 0; ks < 2; ++ks) {
                aq[ks][0] = h2u(acc[2*ks][0],   acc[2*ks][1]);     // row g,   k 2t,2t+1
                aq[ks][1] = h2u(acc[2*ks][2],   acc[2*ks][3]);     // row g+8
                aq[ks][2] = h2u(acc[2*ks+1][0], acc[2*ks+1][1]);   // row g,   k 2t+8,2t+9
                aq[ks][3] = h2u(acc[2*ks+1][2], acc[2*ks+1][3]);   // row g+8
            }
            uint32_t bk0[2][2], bk1[2][2];
            #pragma unroll
            for (int ks = 0; ks < 2; ++ks) {
                bk0[ks][0] = h2u(acc[4+2*ks][0],   acc[4+2*ks][1]);
                bk0[ks][1] = h2u(acc[4+2*ks+1][0], acc[4+2*ks+1][1]);
                bk1[ks][0] = h2u(acc[4+2*ks][2],   acc[4+2*ks][3]);
                bk1[ks][1] = h2u(acc[4+2*ks+1][2], acc[4+2*ks+1][3]);
            }
            float csA[4] = {bj0, bj1, 0.0f, 0.0f};   // batch0 (rows g) in e0,e1
            float csB[4] = {0.0f, 0.0f, bj0, bj1};   // batch1 (rows g+8) in e2,e3
            mma16(csA, aq[0][0], aq[0][1], aq[0][2], aq[0][3], bk0[0][0], bk0[0][1]);
            mma16(csA, aq[1][0], aq[1][1], aq[1][2], aq[1][3], bk0[1][0], bk0[1][1]);
            mma16(csB, aq[0][0], aq[0][1], aq[0][2], aq[0][3], bk1[0][0], bk1[0][1]);
            mma16(csB, aq[1][0], aq[1][1], aq[1][2], aq[1][3], bk1[1][0], bk1[1][1]);
            // softmax over 8 slots (2 per lane, reduce across 4-lane t-group);
            // |sim| small -> no max subtraction needed (validated R10).
            float e0 = __expf(csA[0]), e1 = __expf(csA[1]);
            float f0 = __expf(csB[2]), f1 = __expf(csB[3]);
            float s0 = e0 + e1, s1 = f0 + f1;
            s0 += __shfl_xor_sync(FULLM, s0, 1);
            s1 += __shfl_xor_sync(FULLM, s1, 1);
            s0 += __shfl_xor_sync(FULLM, s0, 2);
            s1 += __shfl_xor_sync(FULLM, s1, 2);
            const float i0 = 1.0f / s0, i1 = 1.0f / s1;
            const uint32_t ap0 = h2u(e0 * i0, e1 * i0);   // P rows g   (k 0..7)
            const uint32_t ap3 = h2u(f0 * i1, f1 * i1);   // P rows g+8 (k 8..15)
            float av[4][4];
            #pragma unroll
            for (int nt = 0; nt < 4; ++nt) {
                const uint32_t bv0 = movm(h2u(acc[8+nt][0], acc[8+nt][1]));
                const uint32_t bv1 = movm(h2u(acc[8+nt][2], acc[8+nt][3]));
                av[nt][0] = 0.0f; av[nt][1] = 0.0f; av[nt][2] = 0.0f; av[nt][3] = 0.0f;
                mma16(av[nt], ap0, 0u, 0u, ap3, bv0, bv1);
            }
            #pragma unroll
            for (int n = 0; n < 12; ++n)
                #pragma unroll
                for (int e = 0; e < 4; ++e) acc[n][e] = 0.0f;

            // ---- GEMM2 rank-32 update: acc2 += a2_h @ w2_h ----
            uint32_t af[2][4];
            #pragma unroll
            for (int ks2 = 0; ks2 < 2; ++ks2) {
                af[ks2][0] = h2u(av[2*ks2][0],   av[2*ks2][1]);
                af[ks2][1] = h2u(av[2*ks2][2],   av[2*ks2][3]);
                af[ks2][2] = h2u(av[2*ks2+1][0], av[2*ks2+1][1]);
                af[ks2][3] = h2u(av[2*ks2+1][2], av[2*ks2+1][3]);
            }
            const uint4* const b24 = (const uint4*)(smem + SM_B2 + (h & 1) * B2_SLOT);
            #pragma unroll
            for (int ks2 = 0; ks2 < 2; ++ks2) {
                #pragma unroll
                for (int ntp = 0; ntp < 16; ++ntp) {
                    const uint4 fb = b24[(ks2 * 16 + ntp) * 32 + lane];
                    mma16(acc2[2*ntp],     af[ks2][0], af[ks2][1], af[ks2][2], af[ks2][3],
                          fb.x, fb.y);
                    mma16(acc2[2*ntp + 1], af[ks2][0], af[ks2][1], af[ks2][2], af[ks2][3],
                          fb.z, fb.w);
                }
            }
        }
    }

    // ---- epilogue: acc2 -> out (lane-direct STG.64) ----
    float* od  = out + ((size_t)cta * 128 + w16 + g) * 256 + 2 * t;
    float* od2 = od + 8 * 256;
    #pragma unroll
    for (int nt = 0; nt < 32; ++nt) {
        *(float2*)(od  + nt * 8) = make_float2(acc2[nt][0], acc2[nt][1]);
        *(float2*)(od2 + nt * 8) = make_float2(acc2[nt][2], acc2[nt][3]);
    }
}

extern "C" void kernel_launch(void* const* d_in, const int* in_sizes, int n_in,
                              void* d_out, int out_size) {
    const float* x    = (const float*)d_in[0];
    const float* lnw  = (const float*)d_in[1];
    const float* lnb  = (const float*)d_in[2];
    const float* wqkv = (const float*)d_in[3];
    const float* wout = (const float*)d_in[4];
    const float* relt = (const float*)d_in[5];
    // d_in[6] (rel_pos_indices) recomputed analytically in-kernel.

    prep_w1<<<768, 256>>>(wqkv);
    prep_w2<<<256, 256>>>(wout);

    cudaFuncSetAttribute(attn_fused, cudaFuncAttributeMaxDynamicSharedMemorySize, K1_SMEM);
    attn_fused<<<2048, 256, K1_SMEM>>>(x, lnw, lnb, relt, (float*)d_out);
}

// round 15
// speedup vs baseline: 1.0116x; 1.0116x over previous
#include <cuda_runtime.h>
#include <cuda_fp16.h>
#include <cstdint>

// ============================================================
// Attention1D fully fused: LN -> QKV GEMM -> 8-head window attention
//   -> output GEMM. One kernel, persistent register accumulators.
// fp16 mma.sync m16n8k16 everywhere (incl. attention: c->a/b frag repack,
// movmatrix V-transpose, block-diagonal PV MMA).
// R14: single merged prep kernel (2 launches/call -> ncu lands on fused),
// ldmatrix.x4 A-fragment loads. tcgen05 unavailable (PTX = compute_103).
// ============================================================

#define FULLM 0xffffffffu

// B1 frags: [cid(16)=h*2+qq][ks(8)][ntp(6)][lane(32)][q4(4)] uint32  (384KB)
__device__ __align__(16) uint32_t g_w1t[196608];
// B2 frags: [h(8)][ks2(2)][ntp(16)][lane(32)][q4(4)] uint32          (128KB)
__device__ __align__(16) uint32_t g_w2t[65536];

static __device__ __forceinline__ void mma16(float* c, uint32_t a0, uint32_t a1,
                                             uint32_t a2, uint32_t a3,
                                             uint32_t b0, uint32_t b1) {
    asm volatile(
        "mma.sync.aligned.m16n8k16.row.col.f32.f16.f16.f32 "
        "{%0,%1,%2,%3}, {%4,%5,%6,%7}, {%8,%9}, {%0,%1,%2,%3};"
        : "+f"(c[0]), "+f"(c[1]), "+f"(c[2]), "+f"(c[3])
        : "r"(a0), "r"(a1), "r"(a2), "r"(a3), "r"(b0), "r"(b1));
}
static __device__ __forceinline__ uint32_t h2u(float a, float b) {
    __half2 h = __floats2half2_rn(a, b);
    return *(uint32_t*)&h;
}
static __device__ __forceinline__ uint32_t movm(uint32_t s) {
    uint32_t d;
    asm("movmatrix.sync.aligned.m8n8.trans.b16 %0, %1;" : "=r"(d) : "r"(s));
    return d;
}
#define LDSM4(a0, a1, a2, a3, addr)                                        \
    asm volatile("ldmatrix.sync.aligned.m8n8.x4.shared.b16 {%0,%1,%2,%3}, [%4];" \
                 : "=r"(a0), "=r"(a1), "=r"(a2), "=r"(a3) : "r"(addr))
static __device__ __forceinline__ uint32_t smem_u32(const void* p) {
    uint32_t a;
    asm("{ .reg .u64 t; cvta.to.shared.u64 t, %1; cvt.u32.u64 %0, t; }" : "=r"(a) : "l"(p));
    return a;
}
#define CP16(dst, src) \
    asm volatile("cp.async.cg.shared.global [%0], [%1], 16;" :: "r"(dst), "l"(src))
#define CP_COMMIT() asm volatile("cp.async.commit_group;" ::: "memory")
#define CP_WAIT(n)  asm volatile("cp.async.wait_group %0;" :: "n"(n) : "memory")

// ---------------- merged weight prep (fp16 round + fragment transpose) ----------------
// Attention scale (32^-0.5) folded into the q-columns of w1.
__global__ void prep_w(const float* __restrict__ wqkv, const float* __restrict__ wout) {
    if (blockIdx.x < 768) {
        int p = blockIdx.x * 256 + threadIdx.x;      // < 196608
        int q4   = p & 3;
        int lane = (p >> 2) & 31;
        int rest = p >> 7;                           // 0..1535
        int ntp = rest % 6;
        int r2  = rest / 6;                          // 0..255
        int ks  = r2 & 7;
        int cid = r2 >> 3;                           // 0..15
        int h = cid >> 1, qq = cid & 1;
        int t = lane & 3, g = lane >> 2;
        int nt  = 2 * ntp + (q4 >> 1);
        int b01 = q4 & 1;
        int k0 = qq * 128 + ks * 16 + b01 * 8 + 2 * t;
        int s = nt >> 2;                             // 0=q,1=k,2=v
        int col = s * 256 + h * 32 + (nt & 3) * 8 + g;
        float sc = (s == 0) ? 0.17677669529663689f : 1.0f;
        g_w1t[p] = h2u(wqkv[k0 * 768 + col] * sc, wqkv[(k0 + 1) * 768 + col] * sc);
    } else {
        int p = (blockIdx.x - 768) * 256 + threadIdx.x;  // < 65536
        int q4   = p & 3;
        int lane = (p >> 2) & 31;
        int ntp  = (p >> 7) & 15;
        int ks2  = (p >> 11) & 1;
        int h    = p >> 12;
        int t = lane & 3, g = lane >> 2;
        int nt  = 2 * ntp + (q4 >> 1);
        int b01 = q4 & 1;
        int k0 = h * 32 + ks2 * 16 + b01 * 8 + 2 * t;
        int n  = nt * 8 + g;
        g_w2t[p] = h2u(wout[k0 * 256 + n], wout[(k0 + 1) * 256 + n]);
    }
}

// ============================================================
// Fused kernel. 256 threads (8 warps), warp = m16 rows.
// smem: xn 64KB | B1 ring 3x24KB | B2 ring 2x16KB  = 172032 B
// ============================================================
#define B1_SLOT 24576
#define B2_SLOT 16384
#define SM_B1   65536
#define SM_B2   (65536 + 3 * B1_SLOT)
#define K1_SMEM (65536 + 3 * B1_SLOT + 2 * B2_SLOT)

__global__ void __launch_bounds__(256, 1) attn_fused(
    const float* __restrict__ x, const float* __restrict__ lnw,
    const float* __restrict__ lnb, const float* __restrict__ relt,
    float* __restrict__ out)
{
    extern __shared__ __align__(16) char smem[];
    __half* const sxn = (__half*)smem;                // 32768 halves
    const int tid  = threadIdx.x;
    const int wid  = tid >> 5;
    const int lane = tid & 31;
    const int g = lane >> 2, t = lane & 3;
    const int cta = blockIdx.x;
    const uint32_t sxn_u   = smem_u32(smem);
    const uint32_t smem_b1 = sxn_u + SM_B1;
    const uint32_t smem_b2 = sxn_u + SM_B2;

    auto stage = [&](int cid2, bool withB2, int h2) {
        uint32_t dst = smem_b1 + (uint32_t)(cid2 % 3) * (uint32_t)B1_SLOT + (uint32_t)tid * 16u;
        const char* src = (const char*)g_w1t + cid2 * B1_SLOT + tid * 16;
        #pragma unroll
        for (int i = 0; i < 6; ++i) CP16(dst + i * 4096u, src + i * 4096);
        if (withB2) {
            uint32_t d2 = smem_b2 + (uint32_t)(h2 & 1) * (uint32_t)B2_SLOT + (uint32_t)tid * 16u;
            const char* s2 = (const char*)g_w2t + h2 * B2_SLOT + tid * 16;
            #pragma unroll
            for (int i = 0; i < 4; ++i) CP16(d2 + i * 4096u, s2 + i * 4096);
        }
        CP_COMMIT();
    };
    stage(0, true, 0);                                // chunk 0 + B2_0
    stage(1, false, 0);

    // ---- LayerNorm -> xor-swizzled row-major fp16 xn (overlaps cp.async) ----
    {
        const float* xr = x + (size_t)cta * 128 * 256;
        const float4 w0 = *(const float4*)(lnw + lane * 4);
        const float4 w1 = *(const float4*)(lnw + 128 + lane * 4);
        const float4 b0 = *(const float4*)(lnb + lane * 4);
        const float4 b1 = *(const float4*)(lnb + 128 + lane * 4);
        #pragma unroll 2
        for (int rr = 0; rr < 16; ++rr) {
            const int r = wid * 16 + rr;
            const float4 xa = *(const float4*)(xr + r * 256 + lane * 4);
            const float4 xb = *(const float4*)(xr + r * 256 + 128 + lane * 4);
            float s  = xa.x + xa.y + xa.z + xa.w + xb.x + xb.y + xb.z + xb.w;
            float ss = xa.x*xa.x + xa.y*xa.y + xa.z*xa.z + xa.w*xa.w
                     + xb.x*xb.x + xb.y*xb.y + xb.z*xb.z + xb.w*xb.w;
            #pragma unroll
            for (int o2 = 16; o2; o2 >>= 1) {
                s  += __shfl_xor_sync(FULLM, s,  o2);
                ss += __shfl_xor_sync(FULLM, ss, o2);
            }
            const float mu   = s * (1.0f / 256.0f);
            const float rstd = rsqrtf(ss * (1.0f / 256.0f) - mu * mu + 1e-5f);
            const int srw = (r & 7) << 3;             // half-index XOR swizzle
            uint2 pa, pb;
            pa.x = h2u((xa.x - mu) * rstd * w0.x + b0.x, (xa.y - mu) * rstd * w0.y + b0.y);
            pa.y = h2u((xa.z - mu) * rstd * w0.z + b0.z, (xa.w - mu) * rstd * w0.w + b0.w);
            pb.x = h2u((xb.x - mu) * rstd * w1.x + b1.x, (xb.y - mu) * rstd * w1.y + b1.y);
            pb.y = h2u((xb.z - mu) * rstd * w1.z + b1.z, (xb.w - mu) * rstd * w1.w + b1.w);
            *(uint2*)(sxn + r * 256 + ((lane * 4) ^ srw))         = pa;
            *(uint2*)(sxn + r * 256 + ((128 + lane * 4) ^ srw))   = pb;
        }
    }

    float acc[12][4];                 // GEMM1 accum (q|k|v of current head)
    #pragma unroll
    for (int n = 0; n < 12; ++n)
        #pragma unroll
        for (int e = 0; e < 4; ++e) acc[n][e] = 0.0f;

    float acc2[32][4];                // GEMM2 accum (m16 x n256, all heads)
    #pragma unroll
    for (int n = 0; n < 32; ++n)
        #pragma unroll
        for (int e = 0; e < 4; ++e) acc2[n][e] = 0.0f;

    const int w16 = wid * 16;
    // ldmatrix lane addressing: row = w16 + (lane&15), k-half = lane>>4
    const uint32_t arow = sxn_u + (uint32_t)(w16 + (lane & 15)) * 512u;
    const uint32_t sxr  = (uint32_t)((lane & 7) << 3);    // (row&7)<<3
    const uint32_t kh8  = (uint32_t)((lane >> 4) << 3);
    float bj0 = 0.0f, bj1 = 0.0f;     // rel-pos bias (slot g vs slots 2t / 2t+1)

    #pragma unroll 1
    for (int cid = 0; cid < 16; ++cid) {
        const int h = cid >> 1, qq = cid & 1;
        if (cid == 15) { CP_WAIT(0); } else { CP_WAIT(1); }
        __syncthreads();                              // chunk cid (and its B2) ready
        if (cid + 2 < 16) stage(cid + 2, ((cid + 2) & 1) == 0, (cid + 2) >> 1);

        if (qq == 0) {
            const int j0 = 2 * t, j1 = 2 * t + 1;
            const int r0 = (g >= 1 && j0 >= 1) ? (g - j0 + 6) : 13;
            const int r1 = (g >= 1) ? (g - j1 + 6) : 13;
            bj0 = __ldg(relt + r0 * 8 + h);
            bj1 = __ldg(relt + r1 * 8 + h);
        }

        // ---- GEMM1 on chunk: K=128 (8 k16-steps), warp tile m16 x n96 ----
        const uint4* const bw4 = (const uint4*)(smem + SM_B1 + (cid % 3) * B1_SLOT);
        #pragma unroll
        for (int ks = 0; ks < 8; ++ks) {
            const uint32_t col = ((uint32_t)(qq << 7) | (uint32_t)(ks << 4) | kh8) ^ sxr;
            uint32_t a0, a1, a2, a3;
            LDSM4(a0, a1, a2, a3, arow + (col << 1));
            #pragma unroll
            for (int ntp = 0; ntp < 6; ++ntp) {
                const uint4 fb = bw4[(ks * 6 + ntp) * 32 + lane];
                mma16(acc[2*ntp],     a0, a1, a2, a3, fb.x, fb.y);
                mma16(acc[2*ntp + 1], a0, a1, a2, a3, fb.z, fb.w);
            }
        }

        if (qq == 1) {
            // ================== attention for head h (MMA-based) ==================
            uint32_t aq[2][4];
            #pragma unroll
            for (int ks = 0; ks < 2; ++ks) {
                aq[ks][0] = h2u(acc[2*ks][0],   acc[2*ks][1]);
                aq[ks][1] = h2u(acc[2*ks][2],   acc[2*ks][3]);
                aq[ks][2] = h2u(acc[2*ks+1][0], acc[2*ks+1][1]);
                aq[ks][3] = h2u(acc[2*ks+1][2], acc[2*ks+1][3]);
            }
            uint32_t bk0[2][2], bk1[2][2];
            #pragma unroll
            for (int ks = 0; ks < 2; ++ks) {
                bk0[ks][0] = h2u(acc[4+2*ks][0],   acc[4+2*ks][1]);
                bk0[ks][1] = h2u(acc[4+2*ks+1][0], acc[4+2*ks+1][1]);
                bk1[ks][0] = h2u(acc[4+2*ks][2],   acc[4+2*ks][3]);
                bk1[ks][1] = h2u(acc[4+2*ks+1][2], acc[4+2*ks+1][3]);
            }
            float csA[4] = {bj0, bj1, 0.0f, 0.0f};   // batch0 (rows g) in e0,e1
            float csB[4] = {0.0f, 0.0f, bj0, bj1};   // batch1 (rows g+8) in e2,e3
            mma16(csA, aq[0][0], aq[0][1], aq[0][2], aq[0][3], bk0[0][0], bk0[0][1]);
            mma16(csA, aq[1][0], aq[1][1], aq[1][2], aq[1][3], bk0[1][0], bk0[1][1]);
            mma16(csB, aq[0][0], aq[0][1], aq[0][2], aq[0][3], bk1[0][0], bk1[0][1]);
            mma16(csB, aq[1][0], aq[1][1], aq[1][2], aq[1][3], bk1[1][0], bk1[1][1]);
            // softmax (|sim| small -> no max subtraction; validated R10)
            float e0 = __expf(csA[0]), e1 = __expf(csA[1]);
            float f0 = __expf(csB[2]), f1 = __expf(csB[3]);
            float s0 = e0 + e1, s1 = f0 + f1;
            s0 += __shfl_xor_sync(FULLM, s0, 1);
            s1 += __shfl_xor_sync(FULLM, s1, 1);
            s0 += __shfl_xor_sync(FULLM, s0, 2);
            s1 += __shfl_xor_sync(FULLM, s1, 2);
            const float i0 = 1.0f / s0, i1 = 1.0f / s1;
            const uint32_t ap0 = h2u(e0 * i0, e1 * i0);   // P rows g   (k 0..7)
            const uint32_t ap3 = h2u(f0 * i1, f1 * i1);   // P rows g+8 (k 8..15)
            float av[4][4];
            #pragma unroll
            for (int nt = 0; nt < 4; ++nt) {
                const uint32_t bv0 = movm(h2u(acc[8+nt][0], acc[8+nt][1]));
                const uint32_t bv1 = movm(h2u(acc[8+nt][2], acc[8+nt][3]));
                av[nt][0] = 0.0f; av[nt][1] = 0.0f; av[nt][2] = 0.0f; av[nt][3] = 0.0f;
                mma16(av[nt], ap0, 0u, 0u, ap3, bv0, bv1);
            }
            #pragma unroll
            for (int n = 0; n < 12; ++n)
                #pragma unroll
                for (int e = 0; e < 4; ++e) acc[n][e] = 0.0f;

            // ---- GEMM2 rank-32 update: acc2 += a2_h @ w2_h ----
            uint32_t af[2][4];
            #pragma unroll
            for (int ks2 = 0; ks2 < 2; ++ks2) {
                af[ks2][0] = h2u(av[2*ks2][0],   av[2*ks2][1]);
                af[ks2][1] = h2u(av[2*ks2][2],   av[2*ks2][3]);
                af[ks2][2] = h2u(av[2*ks2+1][0], av[2*ks2+1][1]);
                af[ks2][3] = h2u(av[2*ks2+1][2], av[2*ks2+1][3]);
            }
            const uint4* const b24 = (const uint4*)(smem + SM_B2 + (h & 1) * B2_SLOT);
            #pragma unroll
            for (int ks2 = 0; ks2 < 2; ++ks2) {
                #pragma unroll
                for (int ntp = 0; ntp < 16; ++ntp) {
                    const uint4 fb = b24[(ks2 * 16 + ntp) * 32 + lane];
                    mma16(acc2[2*ntp],     af[ks2][0], af[ks2][1], af[ks2][2], af[ks2][3],
                          fb.x, fb.y);
                    mma16(acc2[2*ntp + 1], af[ks2][0], af[ks2][1], af[ks2][2], af[ks2][3],
                          fb.z, fb.w);
                }
            }
        }
    }

    // ---- epilogue: acc2 -> out (lane-direct STG.64) ----
    float* od  = out + ((size_t)cta * 128 + w16 + g) * 256 + 2 * t;
    float* od2 = od + 8 * 256;
    #pragma unroll
    for (int nt = 0; nt < 32; ++nt) {
        *(float2*)(od  + nt * 8) = make_float2(acc2[nt][0], acc2[nt][1]);
        *(float2*)(od2 + nt * 8) = make_float2(acc2[nt][2], acc2[nt][3]);
    }
}

extern "C" void kernel_launch(void* const* d_in, const int* in_sizes, int n_in,
                              void* d_out, int out_size) {
    const float* x    = (const float*)d_in[0];
    const float* lnw  = (const float*)d_in[1];
    const float* lnb  = (const float*)d_in[2];
    const float* wqkv = (const float*)d_in[3];
    const float* wout = (const float*)d_in[4];
    const float* relt = (const float*)d_in[5];
    // d_in[6] (rel_pos_indices) recomputed analytically in-kernel.

    prep_w<<<1024, 256>>>(wqkv, wout);

    cudaFuncSetAttribute(attn_fused, cudaFuncAttributeMaxDynamicSharedMemorySize, K1_SMEM);
    attn_fused<<<2048, 256, K1_SMEM>>>(x, lnw, lnb, relt, (float*)d_out);
}